// round 3
// baseline (speedup 1.0000x reference)
#include <cuda_runtime.h>
#include <cuda_fp16.h>

// Problem constants
#define BATCH 4
#define HH 1080
#define WW 1920
#define NLUT 33
#define HW (HH * WW)                   // 2,073,600
#define PAIRS_PER (NLUT * 32 * NLUT)   // 34,848 half2 entries per (b,c): z*33, y0*32, x*33
#define NCOMBO 12                      // 4 batches * 3 channels
#define TOTAL_PAIRS (NCOMBO * PAIRS_PER)
#define SMEM_BYTES (PAIRS_PER * 4)     // 139,392 B
#define SUBS 12                        // CTAs per combo
#define TPB 1024

// Scratch: y-pair-expanded fp16 LUT, per (batch,channel).
// P[((bc*33 + z)*32 + y0)*33 + x] = half2(lut[z][y0][x], lut[z][y0+1][x])
__device__ __half2 g_pairs[TOTAL_PAIRS];

__global__ void build_pairs_kernel(const float* __restrict__ lut) {
    int idx = blockIdx.x * blockDim.x + threadIdx.x;
    if (idx >= TOTAL_PAIRS) return;
    int x = idx % NLUT;
    int t = idx / NLUT;
    int y0 = t % 32; t /= 32;
    int z = t % NLUT;
    int bc = t / NLUT;
    int s = bc * (NLUT * NLUT * NLUT) + (z * NLUT + y0) * NLUT + x;
    g_pairs[idx] = __floats2half2_rn(lut[s], lut[s + NLUT]);
}

__device__ __forceinline__ float tap(const __half2* __restrict__ sp,
                                     float x, float y, float z) {
    // Scale by 31.999998 (vs exact 32): guarantees i0 <= 31 so all +1 / +1056
    // accesses are in-bounds. Trilinear interp is continuous across cell
    // boundaries, so the 6e-8 relative coordinate perturbation changes the
    // output by ~1e-6 — far below the table's fp16 quantization.
    float fx = __saturatef(x) * 31.999998f;
    float fy = __saturatef(y) * 31.999998f;
    float fz = __saturatef(z) * 31.999998f;
    int ix = (int)fx;
    int iy = (int)fy;
    int iz = (int)fz;
    float wx = fx - (float)ix;
    float wy = fy - (float)iy;
    float wz = fz - (float)iz;
    __half2 wx2 = __float2half2_rn(wx);

    int base = (iz * 32 + iy) * NLUT + ix;
    __half2 a00 = sp[base];          // z0: (v(y0,x0), v(y1,x0))
    __half2 a01 = sp[base + 1];      // z0: x1
    __half2 a10 = sp[base + 32 * NLUT];     // z1: x0  (+1056)
    __half2 a11 = sp[base + 32 * NLUT + 1]; // z1: x1

    // x-lerp, SIMD over the packed y-pair (fp16)
    __half2 cz0 = __hfma2(wx2, __hsub2(a01, a00), a00); // (c(z0,y0), c(z0,y1))
    __half2 cz1 = __hfma2(wx2, __hsub2(a11, a10), a10); // (c(z1,y0), c(z1,y1))

    // z- and y-lerps in fp32
    float2 f0 = __half22float2(cz0);
    float2 f1 = __half22float2(cz1);
    float cy0 = fmaf(wz, f1.x - f0.x, f0.x);
    float cy1 = fmaf(wz, f1.y - f0.y, f0.y);
    return fmaf(wy, cy1 - cy0, cy0);
}

__global__ void __launch_bounds__(TPB, 1)
lut_apply_kernel(const float* __restrict__ img, float* __restrict__ out) {
    extern __shared__ __half2 s_pairs[];
    const int combo = blockIdx.x % NCOMBO; // interleave: same-batch CTAs co-run (L2 reuse)
    const int sub = blockIdx.x / NCOMBO;   // 0..SUBS-1
    const int b = combo / 3;
    const int c = combo % 3;

    // Stage this combo's pair table into shared memory (16B vector copies).
    {
        const uint4* src = reinterpret_cast<const uint4*>(g_pairs + combo * PAIRS_PER);
        uint4* dst = reinterpret_cast<uint4*>(s_pairs);
        for (int i = threadIdx.x; i < PAIRS_PER / 4; i += TPB)
            dst[i] = src[i];
    }
    __syncthreads();

    const float4* cx = reinterpret_cast<const float4*>(img + (size_t)b * 3 * HW);
    const float4* cy = cx + HW / 4;
    const float4* cz = cy + HW / 4;
    float4* o4 = reinterpret_cast<float4*>(out + (size_t)(b * 3 + c) * HW);

    const int npix4 = HW / 4;
    const int stride = SUBS * TPB;
    for (int p = sub * TPB + threadIdx.x; p < npix4; p += stride) {
        float4 X = cx[p];
        float4 Y = cy[p];
        float4 Z = cz[p];
        float4 R;
        R.x = tap(s_pairs, X.x, Y.x, Z.x);
        R.y = tap(s_pairs, X.y, Y.y, Z.y);
        R.z = tap(s_pairs, X.z, Y.z, Z.z);
        R.w = tap(s_pairs, X.w, Y.w, Z.w);
        o4[p] = R;
    }
}

extern "C" void kernel_launch(void* const* d_in, const int* in_sizes, int n_in,
                              void* d_out, int out_size) {
    const float* img = (const float*)d_in[0]; // (4,3,1080,1920) f32
    const float* lut = (const float*)d_in[1]; // (4,3,33,33,33) f32
    float* out = (float*)d_out;

    cudaFuncSetAttribute(lut_apply_kernel,
                         cudaFuncAttributeMaxDynamicSharedMemorySize, SMEM_BYTES);

    build_pairs_kernel<<<(TOTAL_PAIRS + 255) / 256, 256>>>(lut);
    lut_apply_kernel<<<NCOMBO * SUBS, TPB, SMEM_BYTES>>>(img, out);
}

// round 4
// speedup vs baseline: 1.0478x; 1.0478x over previous
#include <cuda_runtime.h>
#include <cuda_fp16.h>

// Problem constants
#define BATCH 4
#define HH 1080
#define WW 1920
#define NLUT 33
#define HW (HH * WW)                 // 2,073,600
#define PAIRS_PER (NLUT * NLUT * 32) // 34,848 half2 entries per (b,c)
#define NCOMBO 12                    // 4 batches * 3 channels
#define TOTAL_PAIRS (NCOMBO * PAIRS_PER)
#define SMEM_BYTES (PAIRS_PER * 4)   // 139,392 B
#define SUBS 12                      // CTAs per combo
#define TPB 1024

// Scratch: x-pair-expanded fp16 LUT, per (batch,channel).
// entry[((bc*33 + z)*33 + y)*32 + x0] = (lut[z][y][x0], lut[z][y][x0+1])
__device__ __half2 g_pairs[TOTAL_PAIRS];

__global__ void build_pairs_kernel(const float* __restrict__ lut) {
    int idx = blockIdx.x * blockDim.x + threadIdx.x;
    if (idx >= TOTAL_PAIRS) return;
    int x0 = idx & 31;
    int t = idx >> 5;
    int y = t % NLUT; t /= NLUT;
    int z = t % NLUT;
    int bc = t / NLUT;
    int s = bc * (NLUT * NLUT * NLUT) + (z * NLUT + y) * NLUT + x0;
    g_pairs[idx] = __floats2half2_rn(lut[s], lut[s + 1]);
}

__device__ __forceinline__ float tap(const __half2* __restrict__ sp,
                                     float x, float y, float z) {
    // __saturatef clamps to [0,1]; scale by 31.999998 (vs exact 32) so
    // i0 <= 31 always, keeping the +32 / +1056 / +1088 offsets in-bounds.
    // Trilinear interp is continuous across cell boundaries, so the 6e-8
    // relative coordinate perturbation is ~1e-6 in the output — far below
    // the table's fp16 quantization (~1e-4).
    float fx = __saturatef(x) * 31.999998f;
    float fy = __saturatef(y) * 31.999998f;
    float fz = __saturatef(z) * 31.999998f;
    int ix = (int)fx;
    int iy = (int)fy;
    int iz = (int)fz;
    float wx = fx - (float)ix;
    float wy = fy - (float)iy;
    float wz = fz - (float)iz;

    int base = (iz * NLUT + iy) * 32 + ix;
    __half2 q00 = sp[base];                  // (z0,y0): x0,x1 packed
    __half2 q01 = sp[base + 32];             // (z0,y1)
    __half2 q10 = sp[base + NLUT * 32];      // (z1,y0)
    __half2 q11 = sp[base + NLUT * 32 + 32]; // (z1,y1)

    float2 a00 = __half22float2(q00);
    float2 a01 = __half22float2(q01);
    float2 a10 = __half22float2(q10);
    float2 a11 = __half22float2(q11);

    float c00 = fmaf(wx, a00.y - a00.x, a00.x);
    float c01 = fmaf(wx, a01.y - a01.x, a01.x);
    float c10 = fmaf(wx, a10.y - a10.x, a10.x);
    float c11 = fmaf(wx, a11.y - a11.x, a11.x);
    float c0 = fmaf(wy, c01 - c00, c00);
    float c1 = fmaf(wy, c11 - c10, c10);
    return fmaf(wz, c1 - c0, c0);
}

__global__ void __launch_bounds__(TPB, 1)
lut_apply_kernel(const float* __restrict__ img, float* __restrict__ out) {
    extern __shared__ __half2 s_pairs[];
    const int combo = blockIdx.x % NCOMBO; // interleave: same-batch CTAs co-run (L2 reuse)
    const int sub = blockIdx.x / NCOMBO;   // 0..SUBS-1
    const int b = combo / 3;
    const int c = combo % 3;

    // Stage this combo's pair table into shared memory (16B vector copies).
    {
        const uint4* src = reinterpret_cast<const uint4*>(g_pairs + combo * PAIRS_PER);
        uint4* dst = reinterpret_cast<uint4*>(s_pairs);
        for (int i = threadIdx.x; i < PAIRS_PER / 4; i += TPB)
            dst[i] = src[i];
    }
    __syncthreads();

    const float4* cx = reinterpret_cast<const float4*>(img + (size_t)b * 3 * HW);
    const float4* cy = cx + HW / 4;
    const float4* cz = cy + HW / 4;
    float4* o4 = reinterpret_cast<float4*>(out + (size_t)(b * 3 + c) * HW);

    const int npix4 = HW / 4;
    const int stride = SUBS * TPB;
#pragma unroll 2
    for (int p = sub * TPB + threadIdx.x; p < npix4; p += stride) {
        float4 X = cx[p];
        float4 Y = cy[p];
        float4 Z = cz[p];
        float4 R;
        R.x = tap(s_pairs, X.x, Y.x, Z.x);
        R.y = tap(s_pairs, X.y, Y.y, Z.y);
        R.z = tap(s_pairs, X.z, Y.z, Z.z);
        R.w = tap(s_pairs, X.w, Y.w, Z.w);
        o4[p] = R;
    }
}

extern "C" void kernel_launch(void* const* d_in, const int* in_sizes, int n_in,
                              void* d_out, int out_size) {
    const float* img = (const float*)d_in[0]; // (4,3,1080,1920) f32
    const float* lut = (const float*)d_in[1]; // (4,3,33,33,33) f32
    float* out = (float*)d_out;

    cudaFuncSetAttribute(lut_apply_kernel,
                         cudaFuncAttributeMaxDynamicSharedMemorySize, SMEM_BYTES);

    build_pairs_kernel<<<(TOTAL_PAIRS + 255) / 256, 256>>>(lut);
    lut_apply_kernel<<<NCOMBO * SUBS, TPB, SMEM_BYTES>>>(img, out);
}

// round 5
// speedup vs baseline: 1.0997x; 1.0496x over previous
#include <cuda_runtime.h>
#include <cuda_fp16.h>

// Problem constants
#define BATCH 4
#define HH 1080
#define WW 1920
#define NLUT 33
#define HW (HH * WW)                 // 2,073,600
#define PAIRS_PER (NLUT * NLUT * 32) // 34,848 half2 entries per (b,c)
#define NCOMBO 12                    // 4 batches * 3 channels
#define TOTAL_PAIRS (NCOMBO * PAIRS_PER)
#define SMEM_BYTES (PAIRS_PER * 4)   // 139,392 B
#define SUBS 12                      // CTAs per combo
#define TPB 1024

// Scratch: x-pair-expanded fp16 LUT, per (batch,channel).
// entry[((bc*33 + z)*33 + y)*32 + x0] = (lut[z][y][x0], lut[z][y][x0+1])
__device__ __half2 g_pairs[TOTAL_PAIRS];

__global__ void build_pairs_kernel(const float* __restrict__ lut) {
    int idx = blockIdx.x * blockDim.x + threadIdx.x;
    if (idx >= TOTAL_PAIRS) return;
    int x0 = idx & 31;
    int t = idx >> 5;
    int y = t % NLUT; t /= NLUT;
    int z = t % NLUT;
    int bc = t / NLUT;
    int s = bc * (NLUT * NLUT * NLUT) + (z * NLUT + y) * NLUT + x0;
    g_pairs[idx] = __floats2half2_rn(lut[s], lut[s + 1]);
}

__device__ __forceinline__ float tap(const __half2* __restrict__ sp,
                                     float x, float y, float z) {
    // __saturatef clamps to [0,1]; scale by 31.999998 (vs exact 32) so
    // i0 <= 31 always, keeping the +32 / +1056 / +1088 offsets in-bounds.
    // Trilinear interp is continuous across cell boundaries, so the 6e-8
    // relative coordinate perturbation is ~1e-6 in the output — far below
    // the table's fp16 quantization (~1e-4).
    float fx = __saturatef(x) * 31.999998f;
    float fy = __saturatef(y) * 31.999998f;
    float fz = __saturatef(z) * 31.999998f;
    int ix = (int)fx;
    int iy = (int)fy;
    int iz = (int)fz;
    float wx = fx - (float)ix;
    float wy = fy - (float)iy;
    float wz = fz - (float)iz;

    int base = (iz * NLUT + iy) * 32 + ix;
    __half2 q00 = sp[base];                  // (z0,y0): x0,x1 packed
    __half2 q01 = sp[base + 32];             // (z0,y1)
    __half2 q10 = sp[base + NLUT * 32];      // (z1,y0)
    __half2 q11 = sp[base + NLUT * 32 + 32]; // (z1,y1)

    float2 a00 = __half22float2(q00);
    float2 a01 = __half22float2(q01);
    float2 a10 = __half22float2(q10);
    float2 a11 = __half22float2(q11);

    float c00 = fmaf(wx, a00.y - a00.x, a00.x);
    float c01 = fmaf(wx, a01.y - a01.x, a01.x);
    float c10 = fmaf(wx, a10.y - a10.x, a10.x);
    float c11 = fmaf(wx, a11.y - a11.x, a11.x);
    float c0 = fmaf(wy, c01 - c00, c00);
    float c1 = fmaf(wy, c11 - c10, c10);
    return fmaf(wz, c1 - c0, c0);
}

__global__ void __launch_bounds__(TPB, 1)
lut_apply_kernel(const float* __restrict__ img, float* __restrict__ out) {
    extern __shared__ __half2 s_pairs[];
    const int combo = blockIdx.x % NCOMBO; // interleave: same-batch CTAs co-run (L2 reuse)
    const int sub = blockIdx.x / NCOMBO;   // 0..SUBS-1
    const int b = combo / 3;
    const int c = combo % 3;

    const float4* cx = reinterpret_cast<const float4*>(img + (size_t)b * 3 * HW);
    const float4* cy = cx + HW / 4;
    const float4* cz = cy + HW / 4;
    float4* o4 = reinterpret_cast<float4*>(out + (size_t)(b * 3 + c) * HW);

    const int npix4 = HW / 4;     // 518,400
    const int stride = SUBS * TPB;

    // Prefetch iteration 0's image data BEFORE staging — these LDGs don't
    // depend on shared memory, so their DRAM latency overlaps the table copy.
    int p = sub * TPB + threadIdx.x;   // always < npix4
    float4 X = cx[p];
    float4 Y = cy[p];
    float4 Z = cz[p];

    // Stage this combo's pair table into shared memory (16B vector copies),
    // fully unrolled so all 9 LDGs are in flight together.
    {
        const uint4* src = reinterpret_cast<const uint4*>(g_pairs + combo * PAIRS_PER);
        uint4* dst = reinterpret_cast<uint4*>(s_pairs);
        const int n16 = PAIRS_PER / 4; // 8712
#pragma unroll
        for (int k = 0; k < 9; k++) {
            int i = threadIdx.x + k * TPB;
            if (i < n16) dst[i] = src[i];
        }
    }
    __syncthreads();

    // Software-pipelined main loop: next iteration's global loads issue
    // before this iteration's (LDS-heavy) tap work consumes the current data.
#pragma unroll 1
    for (; p < npix4; p += stride) {
        int pn = min(p + stride, npix4 - 1);  // branchless prefetch guard
        float4 Xn = cx[pn];
        float4 Yn = cy[pn];
        float4 Zn = cz[pn];

        float4 R;
        R.x = tap(s_pairs, X.x, Y.x, Z.x);
        R.y = tap(s_pairs, X.y, Y.y, Z.y);
        R.z = tap(s_pairs, X.z, Y.z, Z.z);
        R.w = tap(s_pairs, X.w, Y.w, Z.w);
        o4[p] = R;

        X = Xn; Y = Yn; Z = Zn;
    }
}

extern "C" void kernel_launch(void* const* d_in, const int* in_sizes, int n_in,
                              void* d_out, int out_size) {
    const float* img = (const float*)d_in[0]; // (4,3,1080,1920) f32
    const float* lut = (const float*)d_in[1]; // (4,3,33,33,33) f32
    float* out = (float*)d_out;

    cudaFuncSetAttribute(lut_apply_kernel,
                         cudaFuncAttributeMaxDynamicSharedMemorySize, SMEM_BYTES);

    build_pairs_kernel<<<(TOTAL_PAIRS + 255) / 256, 256>>>(lut);
    lut_apply_kernel<<<NCOMBO * SUBS, TPB, SMEM_BYTES>>>(img, out);
}